// round 15
// baseline (speedup 1.0000x reference)
#include <cuda_runtime.h>
#include <cuda_fp16.h>
#include <mma.h>
#include <math.h>

using namespace nvcuda;

// ---------------------------------------------------------------------------
// CapsNet forward, fully fused, 1 CTA / batch element, 1024 threads.
// Gram trick: routing never materializes pred.
//   xc[o,c]=sum_i c[o,i]x[c,i];  y[o]=G[o]xc[o]+C*BW[o]  (G=W W^T, fp16)
//   |s|^2=xc.y+C*sB; v=alpha*s;  db[o,i]=alpha*(sum_c y[o,c]x[c,i]+sB)
// R15 = R14 + fully-unrolled G/W streaming loops (raise LDG MLP 8 -> ~12-16,
// halving exposed L2 latency in the dominant y phase). Conv via tensor-core
// im2col with fused bias/relu/squash epilogue; it==2 skips the G stream
// (|s|^2 = |W xc + C B|^2). xc and db GEMMs on tensor cores.
// ---------------------------------------------------------------------------

#define SD  68                   // fp32 row stride
#define SDS 66                   // PS stride
#define LDH 72                   // half row stride (144B rows)

#define XS_OFF   0               // xs[c][i] fp32 (conv input only)      4352
#define XC_OFF   4352            // xc[o][c] fp32 / db-D / conv-out      4352
#define CT_OFF   8704            // ct[i][o] fp32 E / z scratch          4352
#define XSH_OFF  13056           // xs_h[c][i] half 64x72                2304
#define CSH_OFF  15360           // cs_h[o][i] half                      2304
#define YSH_OFF  17664           // ys_h[o][c] half                      2304
#define PS_OFF   19968           // 16x66 fp32                           1056
#define AUX_OFF  21024           // al[64]|sB[64]|CvP[128]
#define IM2_OFF  13056           // im2col half 576x64 overlay
#define SMEM_FLOATS 31552
#define SMEM_BYTES (SMEM_FLOATS * 4)

__device__ __align__(16) __half g_G1h[64 * 64 * 64];
__device__ __align__(16) __half g_G2h[10 * 64 * 64];
__device__ __align__(16) __half g_W1h[64 * 64 * 64];
__device__ __align__(16) __half g_Wbh[64 * 576];
__device__ float g_BW1[64 * 64];
__device__ float g_Bn1[64];
__device__ float g_BW2[10 * 64];
__device__ float g_Bn2[16];

// ---------------------------------------------------------------------------
__global__ void gram_kernel(const float* __restrict__ W1, const float* __restrict__ b1,
                            const float* __restrict__ W2, const float* __restrict__ b2,
                            const float* __restrict__ Wb)
{
    __shared__ float ws[64 * SD];
    __shared__ float bsv[64];
    int blk = blockIdx.x;
    const float* W;
    const float* bias;
    __half* G; float* BW; float* Bn;
    int o;
    if (blk < 64) { o = blk;      W = W1; bias = b1; G = g_G1h + o * 4096; BW = g_BW1 + o * 64; Bn = g_Bn1 + o; }
    else          { o = blk - 64; W = W2; bias = b2; G = g_G2h + o * 4096; BW = g_BW2 + o * 64; Bn = g_Bn2 + o; }
    int tid = threadIdx.x;  // 256

    for (int p = tid; p < 64 * 16; p += 256) {
        int d = p >> 4, q = p & 15;
        float4 v = ((const float4*)(W + (o * 64 + d) * 64))[q];
        ws[d * SD + q * 4 + 0] = v.x;
        ws[d * SD + q * 4 + 1] = v.y;
        ws[d * SD + q * 4 + 2] = v.z;
        ws[d * SD + q * 4 + 3] = v.w;
    }
    if (tid < 64) bsv[tid] = bias[o * 64 + tid];
    __syncthreads();

    for (int p = tid; p < 64 * 16; p += 256) {
        int c = p >> 4, c4 = (p & 15) * 4;
        float a0 = 0.f, a1 = 0.f, a2 = 0.f, a3 = 0.f;
        #pragma unroll 4
        for (int d = 0; d < 64; d++) {
            float wc = ws[d * SD + c];
            a0 += wc * ws[d * SD + c4 + 0];
            a1 += wc * ws[d * SD + c4 + 1];
            a2 += wc * ws[d * SD + c4 + 2];
            a3 += wc * ws[d * SD + c4 + 3];
        }
        G[c * 64 + c4 + 0] = __float2half_rn(a0);
        G[c * 64 + c4 + 1] = __float2half_rn(a1);
        G[c * 64 + c4 + 2] = __float2half_rn(a2);
        G[c * 64 + c4 + 3] = __float2half_rn(a3);
    }
    if (blk < 64) {
        for (int p = tid; p < 2048; p += 256) {
            int d = p >> 5, c2 = (p & 31) * 2;
            __half2 hv = __floats2half2_rn(ws[d * SD + c2], ws[d * SD + c2 + 1]);
            *((__half2*)(g_W1h + ((size_t)o << 12) + d * 64 + c2)) = hv;
        }
        for (int p = tid; p < 576; p += 256)
            g_Wbh[o * 576 + p] = __float2half_rn(Wb[o * 576 + p]);
    }
    if (tid < 64) {
        float acc = 0.f;
        for (int d = 0; d < 64; d++) acc += bsv[d] * ws[d * SD + tid];
        BW[tid] = acc;
    }
    if (tid == 64) {
        float acc = 0.f;
        for (int d = 0; d < 64; d++) acc += bsv[d] * bsv[d];
        *Bn = acc;
    }
}

// ---------------------------------------------------------------------------
// One capsule layer, 3 routing iterations. O = 64 or 10 (even).
// ---------------------------------------------------------------------------
__device__ __forceinline__ void cap_layer(
    int O, bool is_final,
    const float* __restrict__ W2f, const __half* __restrict__ W1h,
    const float* __restrict__ bias,
    const __half* __restrict__ Gh, const float* __restrict__ BW, const float* __restrict__ Bn,
    const float* __restrict__ b0, float* __restrict__ outp,
    float* sm, int tid)
{
    float* xc  = sm + XC_OFF;          // xc, then db-D
    float* ct  = sm + CT_OFF;          // unnormalized E; z scratch at it==2
    float* PS  = sm + PS_OFF;
    float* al  = sm + AUX_OFF;
    float* sB  = sm + AUX_OFF + 64;
    float* CvP = sm + AUX_OFF + 128;
    __half* xs_h = (__half*)(sm + XSH_OFF);
    __half* cs_h = (__half*)(sm + CSH_OFF);
    __half* ys_h = (__half*)(sm + YSH_OFF);

    const int w = tid >> 5, lane = tid & 31;
    const int ii = tid & 63, gg = tid >> 6;
    const int ngrp4 = (O + 3) >> 2;
    const int o0 = w << 1;                       // y/W phase: warp owns o0, o0+1
    const int seg = lane & 7, rgrp = lane >> 3;

    // ---- E0 = exp(b0) (unnormalized) -> ct; PS partial sums ----
    if (gg < ngrp4) {
        int ob = gg << 2;
        float e0 = __expf(b0[ob * 64 + ii]);
        float e1 = (ob + 1 < O) ? __expf(b0[(ob + 1) * 64 + ii]) : 0.f;
        float e2 = (ob + 2 < O) ? __expf(b0[(ob + 2) * 64 + ii]) : 0.f;
        float e3 = (ob + 3 < O) ? __expf(b0[(ob + 3) * 64 + ii]) : 0.f;
        *(float4*)(ct + ii * SD + ob) = make_float4(e0, e1, e2, e3);
        PS[gg * SDS + ii] = e0 + e1 + e2 + e3;
    }
    __syncthreads();

    for (int it = 0; it < 3; it++) {
        // ---- norm pass: cs_h[o][i] = E*ginv (fp16); Cv partials via shfl ----
        {
            float s = 0.f;
            #pragma unroll
            for (int g2 = 0; g2 < 16; g2++) {
                if (g2 >= ngrp4) break;
                s += PS[g2 * SDS + ii];
            }
            float gi = 1.f / s;
            float c0 = 0.f, c1 = 0.f, c2 = 0.f, c3 = 0.f;
            if (gg < ngrp4) {
                float4 e4 = *(float4*)(ct + ii * SD + (gg << 2));
                c0 = e4.x * gi; c1 = e4.y * gi; c2 = e4.z * gi; c3 = e4.w * gi;
                cs_h[((gg << 2) + 0) * LDH + ii] = __float2half_rn(c0);
                cs_h[((gg << 2) + 1) * LDH + ii] = __float2half_rn(c1);
                cs_h[((gg << 2) + 2) * LDH + ii] = __float2half_rn(c2);
                cs_h[((gg << 2) + 3) * LDH + ii] = __float2half_rn(c3);
            }
            #pragma unroll
            for (int k = 16; k; k >>= 1) {
                c0 += __shfl_xor_sync(0xffffffffu, c0, k);
                c1 += __shfl_xor_sync(0xffffffffu, c1, k);
                c2 += __shfl_xor_sync(0xffffffffu, c2, k);
                c3 += __shfl_xor_sync(0xffffffffu, c3, k);
            }
            if (lane == 0 && gg < ngrp4) {
                float* dst = CvP + ((w & 1) << 6) + (gg << 2);
                dst[0] = c0; dst[1] = c1; dst[2] = c2; dst[3] = c3;
            }
        }
        __syncthreads();

        // ---- xc = c @ x^T via tensor cores (16 warps, 1 tile each) ----
        if (w < 16 && ((w >> 2) << 4) < O) {
            int to = w >> 2, tc = w & 3;
            wmma::fragment<wmma::accumulator, 16, 16, 16, float> fc;
            wmma::fill_fragment(fc, 0.f);
            #pragma unroll
            for (int k = 0; k < 4; k++) {
                wmma::fragment<wmma::matrix_a, 16, 16, 16, __half, wmma::row_major> fa;
                wmma::fragment<wmma::matrix_b, 16, 16, 16, __half, wmma::col_major> fb;
                wmma::load_matrix_sync(fa, cs_h + to * 16 * LDH + k * 16, LDH);
                wmma::load_matrix_sync(fb, xs_h + tc * 16 * LDH + k * 16, LDH);
                wmma::mma_sync(fc, fa, fb, fc);
            }
            wmma::store_matrix_sync(xc + to * 16 * SD + tc * 16, fc, SD, wmma::mem_row_major);
        }
        __syncthreads();

        if (it < 2) {
            // ---- y phase: per-o G GEMV, FULLY unrolled (max LDG MLP) ----
            if (o0 < O) {
                #pragma unroll
                for (int oo = 0; oo < 2; oo++) {
                    int o = o0 + oo;
                    float cf = CvP[o] + CvP[64 + o];
                    const __half* Gp = Gh + ((size_t)o << 12) + (seg << 3);
                    float4 xq0 = *(const float4*)(xc + o * SD + seg * 8);
                    float4 xq1 = *(const float4*)(xc + o * SD + seg * 8 + 4);
                    float nq = 0.f, sbq = 0.f;
                    #pragma unroll
                    for (int rb = 0; rb < 64; rb += 4) {
                        int r = rb + rgrp;
                        uint4 g = *(const uint4*)(Gp + (r << 6));
                        float2 t0 = __half22float2(*(__half2*)&g.x);
                        float2 t1 = __half22float2(*(__half2*)&g.y);
                        float2 t2 = __half22float2(*(__half2*)&g.z);
                        float2 t3 = __half22float2(*(__half2*)&g.w);
                        float p = t0.x * xq0.x + t0.y * xq0.y + t1.x * xq0.z + t1.y * xq0.w
                                + t2.x * xq1.x + t2.y * xq1.y + t3.x * xq1.z + t3.y * xq1.w;
                        p += __shfl_xor_sync(0xffffffffu, p, 1);
                        p += __shfl_xor_sync(0xffffffffu, p, 2);
                        p += __shfl_xor_sync(0xffffffffu, p, 4);   // (G xc)[r]
                        float bwv = BW[o * 64 + r];
                        float yv = p + cf * bwv;
                        float xcr = xc[o * SD + r];
                        nq += yv * xcr;
                        sbq += bwv * xcr;
                        if (seg == 0)
                            ys_h[o * LDH + r] = __float2half_rn(yv);
                    }
                    nq  += __shfl_xor_sync(0xffffffffu, nq, 8);
                    nq  += __shfl_xor_sync(0xffffffffu, nq, 16);
                    sbq += __shfl_xor_sync(0xffffffffu, sbq, 8);
                    sbq += __shfl_xor_sync(0xffffffffu, sbq, 16);
                    if (lane == 0) {
                        float sbf = sbq + cf * Bn[o];
                        float nn = nq + cf * sbf;
                        sB[o] = sbf;
                        al[o] = (nn / (1.f + nn)) * rsqrtf(nn + 1e-8f);
                    }
                }
            }
            __syncthreads();

            // ---- db = y @ x via tensor cores -> D in xc region ----
            if (w < 16 && ((w >> 2) << 4) < O) {
                int to = w >> 2, ti = w & 3;
                wmma::fragment<wmma::accumulator, 16, 16, 16, float> fc;
                wmma::fill_fragment(fc, 0.f);
                #pragma unroll
                for (int k = 0; k < 4; k++) {
                    wmma::fragment<wmma::matrix_a, 16, 16, 16, __half, wmma::row_major> fa;
                    wmma::fragment<wmma::matrix_b, 16, 16, 16, __half, wmma::row_major> fb;
                    wmma::load_matrix_sync(fa, ys_h + to * 16 * LDH + k * 16, LDH);
                    wmma::load_matrix_sync(fb, xs_h + k * 16 * LDH + ti * 16, LDH);
                    wmma::mma_sync(fc, fa, fb, fc);
                }
                wmma::store_matrix_sync(xc + to * 16 * SD + ti * 16, fc, SD, wmma::mem_row_major);
            }
            __syncthreads();

            // ---- epilogue: E = c * exp(al*(db+sB)); new PS partials ----
            if (gg < ngrp4) {
                float e[4];
                float s = 0.f;
                #pragma unroll
                for (int k = 0; k < 4; k++) {
                    int o = (gg << 2) + k;
                    float ev = 0.f;
                    if (o < O) {
                        float dv = xc[o * SD + ii];
                        float cc = __half2float(cs_h[o * LDH + ii]);
                        ev = cc * __expf(al[o] * (dv + sB[o]));
                    }
                    e[k] = ev; s += ev;
                }
                *(float4*)(ct + ii * SD + (gg << 2)) = make_float4(e[0], e[1], e[2], e[3]);
                PS[gg * SDS + ii] = s;
            }
            __syncthreads();
        } else if (!is_final) {
            // ---- it==2: z = W1 xc + Cv*B; |s|^2 = sum z^2 (no G stream) ----
            float* zb = ct;
            if (o0 < O) {
                #pragma unroll
                for (int oo = 0; oo < 2; oo++) {
                    int o = o0 + oo;
                    float cf = CvP[o] + CvP[64 + o];
                    float4 xq0 = *(const float4*)(xc + o * SD + seg * 8);
                    float4 xq1 = *(const float4*)(xc + o * SD + seg * 8 + 4);
                    const __half* Wp = W1h + ((size_t)o << 12) + (seg << 3);
                    float zz = 0.f;
                    #pragma unroll
                    for (int db_ = 0; db_ < 64; db_ += 4) {
                        int d = db_ + rgrp;
                        uint4 g = *(const uint4*)(Wp + (d << 6));
                        float2 t0 = __half22float2(*(__half2*)&g.x);
                        float2 t1 = __half22float2(*(__half2*)&g.y);
                        float2 t2 = __half22float2(*(__half2*)&g.z);
                        float2 t3 = __half22float2(*(__half2*)&g.w);
                        float p = t0.x * xq0.x + t0.y * xq0.y + t1.x * xq0.z + t1.y * xq0.w
                                + t2.x * xq1.x + t2.y * xq1.y + t3.x * xq1.z + t3.y * xq1.w;
                        p += __shfl_xor_sync(0xffffffffu, p, 1);
                        p += __shfl_xor_sync(0xffffffffu, p, 2);
                        p += __shfl_xor_sync(0xffffffffu, p, 4);
                        if (seg == 0) {
                            float z = p + cf * bias[o * 64 + d];
                            zb[o * SD + d] = z;
                            zz += z * z;
                        }
                    }
                    #pragma unroll
                    for (int k = 16; k; k >>= 1)
                        zz += __shfl_xor_sync(0xffffffffu, zz, k);
                    float av = (zz / (1.f + zz)) * rsqrtf(zz + 1e-8f);
                    __syncwarp();
                    float z0 = zb[o * SD + lane], z1 = zb[o * SD + lane + 32];
                    xs_h[lane * LDH + o]        = __float2half_rn(av * z0);
                    xs_h[(lane + 32) * LDH + o] = __float2half_rn(av * z1);
                }
            }
            __syncthreads();
        } else {
            // ---- final it==2: z via fp32 W2; v = al*z -> gmem ----
            float* zb = ct;
            if (o0 < O) {
                const int s16 = lane & 15, rg2 = lane >> 4;
                #pragma unroll
                for (int oo = 0; oo < 2; oo++) {
                    int o = o0 + oo;
                    float cf = CvP[o] + CvP[64 + o];
                    float4 xq = *(const float4*)(xc + o * SD + s16 * 4);
                    const float* Wp = W2f + (size_t)(o * 64) * 64 + s16 * 4;
                    float zz = 0.f;
                    #pragma unroll
                    for (int db_ = 0; db_ < 64; db_ += 2) {
                        int d = db_ + rg2;
                        float4 wv = *(const float4*)(Wp + (d << 6));
                        float p = wv.x * xq.x + wv.y * xq.y + wv.z * xq.z + wv.w * xq.w;
                        p += __shfl_xor_sync(0xffffffffu, p, 1);
                        p += __shfl_xor_sync(0xffffffffu, p, 2);
                        p += __shfl_xor_sync(0xffffffffu, p, 4);
                        p += __shfl_xor_sync(0xffffffffu, p, 8);
                        if (s16 == 0) {
                            float z = p + cf * bias[o * 64 + d];
                            zb[o * SD + d] = z;
                            zz += z * z;
                        }
                    }
                    #pragma unroll
                    for (int k = 16; k; k >>= 1)
                        zz += __shfl_xor_sync(0xffffffffu, zz, k);
                    float av = (zz / (1.f + zz)) * rsqrtf(zz + 1e-8f);
                    __syncwarp();
                    outp[o * 64 + lane]      = av * zb[o * SD + lane];
                    outp[o * 64 + lane + 32] = av * zb[o * SD + lane + 32];
                }
            }
            __syncthreads();
        }
    }
}

// ---------------------------------------------------------------------------
// Main fused kernel: tensor-core conv3x3 (im2col) + fused relu/squash,
// then 3+1 capsule layers.
// ---------------------------------------------------------------------------
__global__ void __launch_bounds__(1024, 1)
caps_kernel(const float* __restrict__ gx,  const float* __restrict__ gbb,
            const float* __restrict__ W2,  const float* __restrict__ b1,
            const float* __restrict__ b2,
            const float* __restrict__ b_basic, const float* __restrict__ b_cls,
            float* __restrict__ out)
{
    extern __shared__ float sm[];
    int tid = threadIdx.x;
    int b = blockIdx.x;
    float* xs    = sm + XS_OFF;
    float* cvout = sm + XC_OFF;
    float* PSc   = sm + PS_OFF;
    float* fac   = sm + AUX_OFF;
    __half* im2  = (__half*)(sm + IM2_OFF);
    __half* xs_h = (__half*)(sm + XSH_OFF);
    const int w = tid >> 5;

    // load x[b]: xs[c][i]
    const float* xb = gx + (size_t)b * 4096;
    {
        int c = tid >> 4, q = tid & 15;
        float4 v = ((const float4*)(xb + c * 64))[q];
        xs[c * SD + q * 4 + 0] = v.x;
        xs[c * SD + q * 4 + 1] = v.y;
        xs[c * SD + q * 4 + 2] = v.z;
        xs[c * SD + q * 4 + 3] = v.w;
    }
    __syncthreads();

    // im2col (div-free): thread handles column n for 4 ci values; 3x3 unrolled.
    {
        int n = tid & 63, cig = tid >> 6;
        int y = n >> 3, x = n & 7;
        for (int cb = 0; cb < 64; cb += 16) {
            int ci = cb + cig;
            const float* xrow = xs + ci * SD;
            __half* dst = im2 + (ci * 9) * 64 + n;
            #pragma unroll
            for (int ky = 0; ky < 3; ky++) {
                int yy = y + ky - 1;
                bool yok = (unsigned)yy < 8u;
                #pragma unroll
                for (int kx = 0; kx < 3; kx++) {
                    int xx = x + kx - 1;
                    float v = (yok && (unsigned)xx < 8u) ? xrow[yy * 8 + xx] : 0.f;
                    dst[(ky * 3 + kx) * 64] = __float2half_rn(v);
                }
            }
        }
    }
    __syncthreads();

    // conv GEMM: C[co][n] = sum_k Wbh[co][k] * im2[k][n]
    if (w < 16) {
        int to = w >> 2, tn = w & 3;
        wmma::fragment<wmma::accumulator, 16, 16, 16, float> fc;
        wmma::fill_fragment(fc, 0.f);
        for (int k = 0; k < 36; k++) {
            wmma::fragment<wmma::matrix_a, 16, 16, 16, __half, wmma::row_major> fa;
            wmma::fragment<wmma::matrix_b, 16, 16, 16, __half, wmma::row_major> fb;
            wmma::load_matrix_sync(fa, g_Wbh + to * 16 * 576 + k * 16, 576);
            wmma::load_matrix_sync(fb, im2 + k * 16 * 64 + tn * 16, 64);
            wmma::mma_sync(fc, fa, fb, fc);
        }
        wmma::store_matrix_sync(cvout + to * 16 * SD + tn * 16, fc, SD, wmma::mem_row_major);
    }
    __syncthreads();

    // fused bias + relu + squash partials + fp16 store (values in regs)
    {
        int i = tid & 63, g = tid >> 6;
        float vv[4];
        float n2 = 0.f;
        #pragma unroll
        for (int k = 0; k < 4; k++) {
            int c = 4 * g + k;
            float hv = fmaxf(cvout[c * SD + i] + gbb[c], 0.f);
            vv[k] = hv;
            n2 += hv * hv;
        }
        PSc[g * SDS + i] = n2;
        __syncthreads();
        if (tid < 64) {
            float t = 0.f;
            #pragma unroll
            for (int g2 = 0; g2 < 16; g2++) t += PSc[g2 * SDS + tid];
            fac[tid] = (t / (1.f + t)) * rsqrtf(t + 1e-8f);
        }
        __syncthreads();
        float f = fac[i];
        #pragma unroll
        for (int k = 0; k < 4; k++)
            xs_h[(4 * g + k) * LDH + i] = __float2half_rn(vv[k] * f);
    }
    __syncthreads();

    for (int L = 0; L < 3; L++)
        cap_layer(64, false, nullptr, g_W1h, b1, g_G1h, g_BW1, g_Bn1,
                  b_basic + (size_t)(L * 128 + b) * 4096, nullptr, sm, tid);
    cap_layer(10, true, W2, nullptr, b2, g_G2h, g_BW2, g_Bn2,
              b_cls + (size_t)b * 640, out + (size_t)b * 640, sm, tid);
}

// ---------------------------------------------------------------------------
static const float* pick(void* const* d_in, const int* in_sizes, int n_in, int sz) {
    for (int i = 0; i < n_in; i++)
        if (in_sizes[i] == sz) return (const float*)d_in[i];
    return nullptr;
}

extern "C" void kernel_launch(void* const* d_in, const int* in_sizes, int n_in,
                              void* d_out, int out_size)
{
    const float* x       = pick(d_in, in_sizes, n_in, 128 * 64 * 64);
    const float* Wb      = pick(d_in, in_sizes, n_in, 64 * 64 * 9);
    const float* bb      = pick(d_in, in_sizes, n_in, 64);
    const float* W1      = pick(d_in, in_sizes, n_in, 4096 * 64);
    const float* b1      = pick(d_in, in_sizes, n_in, 4096);
    const float* W2      = pick(d_in, in_sizes, n_in, 640 * 64);
    const float* b2      = pick(d_in, in_sizes, n_in, 640);
    const float* b_basic = pick(d_in, in_sizes, n_in, 3 * 128 * 64 * 64);
    const float* b_cls   = pick(d_in, in_sizes, n_in, 128 * 10 * 64);
    float* out = (float*)d_out;

    cudaFuncSetAttribute(caps_kernel, cudaFuncAttributeMaxDynamicSharedMemorySize, SMEM_BYTES);
    gram_kernel<<<74, 256>>>(W1, b1, W2, b2, Wb);
    caps_kernel<<<128, 1024, SMEM_BYTES>>>(x, bb, W2, b1, b2, b_basic, b_cls, out);
}

// round 16
// speedup vs baseline: 1.0193x; 1.0193x over previous
#include <cuda_runtime.h>
#include <cuda_fp16.h>
#include <mma.h>
#include <math.h>

using namespace nvcuda;

// ---------------------------------------------------------------------------
// CapsNet forward, fully fused, 1 CTA / batch element, 1024 threads.
// Gram trick: routing never materializes pred.
//   xc[o,c]=sum_i c[o,i]x[c,i];  y[o]=G[o]xc[o]+C*BW[o]  (G=W W^T, fp16)
//   |s|^2=xc.y+C*sB; v=alpha*s;  db[o,i]=alpha*(sum_c y[o,c]x[c,i]+sB)
// R16 = R14 (best) + adaptive o-per-warp in streaming phases: nox=2 for
// O=64 (identical to R14), nox=1 for the final O=10 layer -> 10 warps with
// one capsule each instead of 5 warps with two, halving the final layer's
// serial phase length. Conv via tensor-core im2col with fused epilogue;
// it==2 skips the G stream; xc and db GEMMs on tensor cores.
// ---------------------------------------------------------------------------

#define SD  68                   // fp32 row stride
#define SDS 66                   // PS stride
#define LDH 72                   // half row stride (144B rows)

#define XS_OFF   0               // xs[c][i] fp32 (conv input only)      4352
#define XC_OFF   4352            // xc[o][c] fp32 / db-D / conv-out      4352
#define CT_OFF   8704            // ct[i][o] fp32 E / z scratch          4352
#define XSH_OFF  13056           // xs_h[c][i] half 64x72                2304
#define CSH_OFF  15360           // cs_h[o][i] half                      2304
#define YSH_OFF  17664           // ys_h[o][c] half                      2304
#define PS_OFF   19968           // 16x66 fp32                           1056
#define AUX_OFF  21024           // al[64]|sB[64]|CvP[128]
#define IM2_OFF  13056           // im2col half 576x64 overlay
#define SMEM_FLOATS 31552
#define SMEM_BYTES (SMEM_FLOATS * 4)

__device__ __align__(16) __half g_G1h[64 * 64 * 64];
__device__ __align__(16) __half g_G2h[10 * 64 * 64];
__device__ __align__(16) __half g_W1h[64 * 64 * 64];
__device__ __align__(16) __half g_Wbh[64 * 576];
__device__ float g_BW1[64 * 64];
__device__ float g_Bn1[64];
__device__ float g_BW2[10 * 64];
__device__ float g_Bn2[16];

// ---------------------------------------------------------------------------
__global__ void gram_kernel(const float* __restrict__ W1, const float* __restrict__ b1,
                            const float* __restrict__ W2, const float* __restrict__ b2,
                            const float* __restrict__ Wb)
{
    __shared__ float ws[64 * SD];
    __shared__ float bsv[64];
    int blk = blockIdx.x;
    const float* W;
    const float* bias;
    __half* G; float* BW; float* Bn;
    int o;
    if (blk < 64) { o = blk;      W = W1; bias = b1; G = g_G1h + o * 4096; BW = g_BW1 + o * 64; Bn = g_Bn1 + o; }
    else          { o = blk - 64; W = W2; bias = b2; G = g_G2h + o * 4096; BW = g_BW2 + o * 64; Bn = g_Bn2 + o; }
    int tid = threadIdx.x;  // 256

    for (int p = tid; p < 64 * 16; p += 256) {
        int d = p >> 4, q = p & 15;
        float4 v = ((const float4*)(W + (o * 64 + d) * 64))[q];
        ws[d * SD + q * 4 + 0] = v.x;
        ws[d * SD + q * 4 + 1] = v.y;
        ws[d * SD + q * 4 + 2] = v.z;
        ws[d * SD + q * 4 + 3] = v.w;
    }
    if (tid < 64) bsv[tid] = bias[o * 64 + tid];
    __syncthreads();

    for (int p = tid; p < 64 * 16; p += 256) {
        int c = p >> 4, c4 = (p & 15) * 4;
        float a0 = 0.f, a1 = 0.f, a2 = 0.f, a3 = 0.f;
        #pragma unroll 4
        for (int d = 0; d < 64; d++) {
            float wc = ws[d * SD + c];
            a0 += wc * ws[d * SD + c4 + 0];
            a1 += wc * ws[d * SD + c4 + 1];
            a2 += wc * ws[d * SD + c4 + 2];
            a3 += wc * ws[d * SD + c4 + 3];
        }
        G[c * 64 + c4 + 0] = __float2half_rn(a0);
        G[c * 64 + c4 + 1] = __float2half_rn(a1);
        G[c * 64 + c4 + 2] = __float2half_rn(a2);
        G[c * 64 + c4 + 3] = __float2half_rn(a3);
    }
    if (blk < 64) {
        for (int p = tid; p < 2048; p += 256) {
            int d = p >> 5, c2 = (p & 31) * 2;
            __half2 hv = __floats2half2_rn(ws[d * SD + c2], ws[d * SD + c2 + 1]);
            *((__half2*)(g_W1h + ((size_t)o << 12) + d * 64 + c2)) = hv;
        }
        for (int p = tid; p < 576; p += 256)
            g_Wbh[o * 576 + p] = __float2half_rn(Wb[o * 576 + p]);
    }
    if (tid < 64) {
        float acc = 0.f;
        for (int d = 0; d < 64; d++) acc += bsv[d] * ws[d * SD + tid];
        BW[tid] = acc;
    }
    if (tid == 64) {
        float acc = 0.f;
        for (int d = 0; d < 64; d++) acc += bsv[d] * bsv[d];
        *Bn = acc;
    }
}

// ---------------------------------------------------------------------------
// One capsule layer, 3 routing iterations. O = 64 or 10 (even).
// ---------------------------------------------------------------------------
__device__ __forceinline__ void cap_layer(
    int O, bool is_final,
    const float* __restrict__ W2f, const __half* __restrict__ W1h,
    const float* __restrict__ bias,
    const __half* __restrict__ Gh, const float* __restrict__ BW, const float* __restrict__ Bn,
    const float* __restrict__ b0, float* __restrict__ outp,
    float* sm, int tid)
{
    float* xc  = sm + XC_OFF;          // xc, then db-D
    float* ct  = sm + CT_OFF;          // unnormalized E; z scratch at it==2
    float* PS  = sm + PS_OFF;
    float* al  = sm + AUX_OFF;
    float* sB  = sm + AUX_OFF + 64;
    float* CvP = sm + AUX_OFF + 128;
    __half* xs_h = (__half*)(sm + XSH_OFF);
    __half* cs_h = (__half*)(sm + CSH_OFF);
    __half* ys_h = (__half*)(sm + YSH_OFF);

    const int w = tid >> 5, lane = tid & 31;
    const int ii = tid & 63, gg = tid >> 6;
    const int ngrp4 = (O + 3) >> 2;
    const int nox = (O > 32) ? 2 : 1;            // capsules per warp in stream phases
    const int o0 = w * nox;
    const int seg = lane & 7, rgrp = lane >> 3;

    // ---- E0 = exp(b0) (unnormalized) -> ct; PS partial sums ----
    if (gg < ngrp4) {
        int ob = gg << 2;
        float e0 = __expf(b0[ob * 64 + ii]);
        float e1 = (ob + 1 < O) ? __expf(b0[(ob + 1) * 64 + ii]) : 0.f;
        float e2 = (ob + 2 < O) ? __expf(b0[(ob + 2) * 64 + ii]) : 0.f;
        float e3 = (ob + 3 < O) ? __expf(b0[(ob + 3) * 64 + ii]) : 0.f;
        *(float4*)(ct + ii * SD + ob) = make_float4(e0, e1, e2, e3);
        PS[gg * SDS + ii] = e0 + e1 + e2 + e3;
    }
    __syncthreads();

    for (int it = 0; it < 3; it++) {
        // ---- norm pass: cs_h[o][i] = E*ginv (fp16); Cv partials via shfl ----
        {
            float s = 0.f;
            for (int g2 = 0; g2 < ngrp4; g2++) s += PS[g2 * SDS + ii];
            float gi = 1.f / s;
            float c0 = 0.f, c1 = 0.f, c2 = 0.f, c3 = 0.f;
            if (gg < ngrp4) {
                float4 e4 = *(float4*)(ct + ii * SD + (gg << 2));
                c0 = e4.x * gi; c1 = e4.y * gi; c2 = e4.z * gi; c3 = e4.w * gi;
                cs_h[((gg << 2) + 0) * LDH + ii] = __float2half_rn(c0);
                cs_h[((gg << 2) + 1) * LDH + ii] = __float2half_rn(c1);
                cs_h[((gg << 2) + 2) * LDH + ii] = __float2half_rn(c2);
                cs_h[((gg << 2) + 3) * LDH + ii] = __float2half_rn(c3);
            }
            #pragma unroll
            for (int k = 16; k; k >>= 1) {
                c0 += __shfl_xor_sync(0xffffffffu, c0, k);
                c1 += __shfl_xor_sync(0xffffffffu, c1, k);
                c2 += __shfl_xor_sync(0xffffffffu, c2, k);
                c3 += __shfl_xor_sync(0xffffffffu, c3, k);
            }
            if (lane == 0 && gg < ngrp4) {
                float* dst = CvP + ((w & 1) << 6) + (gg << 2);
                dst[0] = c0; dst[1] = c1; dst[2] = c2; dst[3] = c3;
            }
        }
        __syncthreads();

        // ---- xc = c @ x^T via tensor cores (16 warps, 1 tile each) ----
        if (w < 16 && ((w >> 2) << 4) < O) {
            int to = w >> 2, tc = w & 3;
            wmma::fragment<wmma::accumulator, 16, 16, 16, float> fc;
            wmma::fill_fragment(fc, 0.f);
            #pragma unroll
            for (int k = 0; k < 4; k++) {
                wmma::fragment<wmma::matrix_a, 16, 16, 16, __half, wmma::row_major> fa;
                wmma::fragment<wmma::matrix_b, 16, 16, 16, __half, wmma::col_major> fb;
                wmma::load_matrix_sync(fa, cs_h + to * 16 * LDH + k * 16, LDH);
                wmma::load_matrix_sync(fb, xs_h + tc * 16 * LDH + k * 16, LDH);
                wmma::mma_sync(fc, fa, fb, fc);
            }
            wmma::store_matrix_sync(xc + to * 16 * SD + tc * 16, fc, SD, wmma::mem_row_major);
        }
        __syncthreads();

        if (it < 2) {
            // ---- y phase: per-o G GEMV with inline reductions ----
            if (o0 < O) {
                for (int oo = 0; oo < nox; oo++) {
                    int o = o0 + oo;
                    float cf = CvP[o] + CvP[64 + o];
                    const __half* Gp = Gh + ((size_t)o << 12) + (seg << 3);
                    float4 xq0 = *(const float4*)(xc + o * SD + seg * 8);
                    float4 xq1 = *(const float4*)(xc + o * SD + seg * 8 + 4);
                    float nq = 0.f, sbq = 0.f;
                    #pragma unroll 8
                    for (int rb = 0; rb < 64; rb += 4) {
                        int r = rb + rgrp;
                        uint4 g = *(const uint4*)(Gp + (r << 6));
                        float2 t0 = __half22float2(*(__half2*)&g.x);
                        float2 t1 = __half22float2(*(__half2*)&g.y);
                        float2 t2 = __half22float2(*(__half2*)&g.z);
                        float2 t3 = __half22float2(*(__half2*)&g.w);
                        float p = t0.x * xq0.x + t0.y * xq0.y + t1.x * xq0.z + t1.y * xq0.w
                                + t2.x * xq1.x + t2.y * xq1.y + t3.x * xq1.z + t3.y * xq1.w;
                        p += __shfl_xor_sync(0xffffffffu, p, 1);
                        p += __shfl_xor_sync(0xffffffffu, p, 2);
                        p += __shfl_xor_sync(0xffffffffu, p, 4);   // (G xc)[r]
                        float bwv = BW[o * 64 + r];
                        float yv = p + cf * bwv;
                        float xcr = xc[o * SD + r];
                        nq += yv * xcr;
                        sbq += bwv * xcr;
                        if (seg == 0)
                            ys_h[o * LDH + r] = __float2half_rn(yv);
                    }
                    nq  += __shfl_xor_sync(0xffffffffu, nq, 8);
                    nq  += __shfl_xor_sync(0xffffffffu, nq, 16);
                    sbq += __shfl_xor_sync(0xffffffffu, sbq, 8);
                    sbq += __shfl_xor_sync(0xffffffffu, sbq, 16);
                    if (lane == 0) {
                        float sbf = sbq + cf * Bn[o];
                        float nn = nq + cf * sbf;
                        sB[o] = sbf;
                        al[o] = (nn / (1.f + nn)) * rsqrtf(nn + 1e-8f);
                    }
                }
            }
            __syncthreads();

            // ---- db = y @ x via tensor cores -> D in xc region ----
            if (w < 16 && ((w >> 2) << 4) < O) {
                int to = w >> 2, ti = w & 3;
                wmma::fragment<wmma::accumulator, 16, 16, 16, float> fc;
                wmma::fill_fragment(fc, 0.f);
                #pragma unroll
                for (int k = 0; k < 4; k++) {
                    wmma::fragment<wmma::matrix_a, 16, 16, 16, __half, wmma::row_major> fa;
                    wmma::fragment<wmma::matrix_b, 16, 16, 16, __half, wmma::row_major> fb;
                    wmma::load_matrix_sync(fa, ys_h + to * 16 * LDH + k * 16, LDH);
                    wmma::load_matrix_sync(fb, xs_h + k * 16 * LDH + ti * 16, LDH);
                    wmma::mma_sync(fc, fa, fb, fc);
                }
                wmma::store_matrix_sync(xc + to * 16 * SD + ti * 16, fc, SD, wmma::mem_row_major);
            }
            __syncthreads();

            // ---- epilogue: E = c * exp(al*(db+sB)); new PS partials ----
            if (gg < ngrp4) {
                float e[4];
                float s = 0.f;
                #pragma unroll
                for (int k = 0; k < 4; k++) {
                    int o = (gg << 2) + k;
                    float ev = 0.f;
                    if (o < O) {
                        float dv = xc[o * SD + ii];
                        float cc = __half2float(cs_h[o * LDH + ii]);
                        ev = cc * __expf(al[o] * (dv + sB[o]));
                    }
                    e[k] = ev; s += ev;
                }
                *(float4*)(ct + ii * SD + (gg << 2)) = make_float4(e[0], e[1], e[2], e[3]);
                PS[gg * SDS + ii] = s;
            }
            __syncthreads();
        } else if (!is_final) {
            // ---- it==2: z = W1 xc + Cv*B; |s|^2 = sum z^2 (no G stream) ----
            float* zb = ct;
            if (o0 < O) {
                for (int oo = 0; oo < nox; oo++) {
                    int o = o0 + oo;
                    float cf = CvP[o] + CvP[64 + o];
                    float4 xq0 = *(const float4*)(xc + o * SD + seg * 8);
                    float4 xq1 = *(const float4*)(xc + o * SD + seg * 8 + 4);
                    const __half* Wp = W1h + ((size_t)o << 12) + (seg << 3);
                    float zz = 0.f;
                    #pragma unroll 8
                    for (int db_ = 0; db_ < 64; db_ += 4) {
                        int d = db_ + rgrp;
                        uint4 g = *(const uint4*)(Wp + (d << 6));
                        float2 t0 = __half22float2(*(__half2*)&g.x);
                        float2 t1 = __half22float2(*(__half2*)&g.y);
                        float2 t2 = __half22float2(*(__half2*)&g.z);
                        float2 t3 = __half22float2(*(__half2*)&g.w);
                        float p = t0.x * xq0.x + t0.y * xq0.y + t1.x * xq0.z + t1.y * xq0.w
                                + t2.x * xq1.x + t2.y * xq1.y + t3.x * xq1.z + t3.y * xq1.w;
                        p += __shfl_xor_sync(0xffffffffu, p, 1);
                        p += __shfl_xor_sync(0xffffffffu, p, 2);
                        p += __shfl_xor_sync(0xffffffffu, p, 4);
                        if (seg == 0) {
                            float z = p + cf * bias[o * 64 + d];
                            zb[o * SD + d] = z;
                            zz += z * z;
                        }
                    }
                    #pragma unroll
                    for (int k = 16; k; k >>= 1)
                        zz += __shfl_xor_sync(0xffffffffu, zz, k);
                    float av = (zz / (1.f + zz)) * rsqrtf(zz + 1e-8f);
                    __syncwarp();
                    float z0 = zb[o * SD + lane], z1 = zb[o * SD + lane + 32];
                    xs_h[lane * LDH + o]        = __float2half_rn(av * z0);
                    xs_h[(lane + 32) * LDH + o] = __float2half_rn(av * z1);
                }
            }
            __syncthreads();
        } else {
            // ---- final it==2: z via fp32 W2; v = al*z -> gmem ----
            float* zb = ct;
            if (o0 < O) {
                const int s16 = lane & 15, rg2 = lane >> 4;
                for (int oo = 0; oo < nox; oo++) {
                    int o = o0 + oo;
                    float cf = CvP[o] + CvP[64 + o];
                    float4 xq = *(const float4*)(xc + o * SD + s16 * 4);
                    const float* Wp = W2f + (size_t)(o * 64) * 64 + s16 * 4;
                    float zz = 0.f;
                    #pragma unroll 8
                    for (int db_ = 0; db_ < 64; db_ += 2) {
                        int d = db_ + rg2;
                        float4 wv = *(const float4*)(Wp + (d << 6));
                        float p = wv.x * xq.x + wv.y * xq.y + wv.z * xq.z + wv.w * xq.w;
                        p += __shfl_xor_sync(0xffffffffu, p, 1);
                        p += __shfl_xor_sync(0xffffffffu, p, 2);
                        p += __shfl_xor_sync(0xffffffffu, p, 4);
                        p += __shfl_xor_sync(0xffffffffu, p, 8);
                        if (s16 == 0) {
                            float z = p + cf * bias[o * 64 + d];
                            zb[o * SD + d] = z;
                            zz += z * z;
                        }
                    }
                    #pragma unroll
                    for (int k = 16; k; k >>= 1)
                        zz += __shfl_xor_sync(0xffffffffu, zz, k);
                    float av = (zz / (1.f + zz)) * rsqrtf(zz + 1e-8f);
                    __syncwarp();
                    outp[o * 64 + lane]      = av * zb[o * SD + lane];
                    outp[o * 64 + lane + 32] = av * zb[o * SD + lane + 32];
                }
            }
            __syncthreads();
        }
    }
}

// ---------------------------------------------------------------------------
// Main fused kernel: tensor-core conv3x3 (im2col) + fused relu/squash,
// then 3+1 capsule layers.
// ---------------------------------------------------------------------------
__global__ void __launch_bounds__(1024, 1)
caps_kernel(const float* __restrict__ gx,  const float* __restrict__ gbb,
            const float* __restrict__ W2,  const float* __restrict__ b1,
            const float* __restrict__ b2,
            const float* __restrict__ b_basic, const float* __restrict__ b_cls,
            float* __restrict__ out)
{
    extern __shared__ float sm[];
    int tid = threadIdx.x;
    int b = blockIdx.x;
    float* xs    = sm + XS_OFF;
    float* cvout = sm + XC_OFF;
    float* PSc   = sm + PS_OFF;
    float* fac   = sm + AUX_OFF;
    __half* im2  = (__half*)(sm + IM2_OFF);
    __half* xs_h = (__half*)(sm + XSH_OFF);
    const int w = tid >> 5;

    // load x[b]: xs[c][i]
    const float* xb = gx + (size_t)b * 4096;
    {
        int c = tid >> 4, q = tid & 15;
        float4 v = ((const float4*)(xb + c * 64))[q];
        xs[c * SD + q * 4 + 0] = v.x;
        xs[c * SD + q * 4 + 1] = v.y;
        xs[c * SD + q * 4 + 2] = v.z;
        xs[c * SD + q * 4 + 3] = v.w;
    }
    __syncthreads();

    // im2col (div-free): thread handles column n for 4 ci values; 3x3 unrolled.
    {
        int n = tid & 63, cig = tid >> 6;
        int y = n >> 3, x = n & 7;
        for (int cb = 0; cb < 64; cb += 16) {
            int ci = cb + cig;
            const float* xrow = xs + ci * SD;
            __half* dst = im2 + (ci * 9) * 64 + n;
            #pragma unroll
            for (int ky = 0; ky < 3; ky++) {
                int yy = y + ky - 1;
                bool yok = (unsigned)yy < 8u;
                #pragma unroll
                for (int kx = 0; kx < 3; kx++) {
                    int xx = x + kx - 1;
                    float v = (yok && (unsigned)xx < 8u) ? xrow[yy * 8 + xx] : 0.f;
                    dst[(ky * 3 + kx) * 64] = __float2half_rn(v);
                }
            }
        }
    }
    __syncthreads();

    // conv GEMM: C[co][n] = sum_k Wbh[co][k] * im2[k][n]
    if (w < 16) {
        int to = w >> 2, tn = w & 3;
        wmma::fragment<wmma::accumulator, 16, 16, 16, float> fc;
        wmma::fill_fragment(fc, 0.f);
        for (int k = 0; k < 36; k++) {
            wmma::fragment<wmma::matrix_a, 16, 16, 16, __half, wmma::row_major> fa;
            wmma::fragment<wmma::matrix_b, 16, 16, 16, __half, wmma::row_major> fb;
            wmma::load_matrix_sync(fa, g_Wbh + to * 16 * 576 + k * 16, 576);
            wmma::load_matrix_sync(fb, im2 + k * 16 * 64 + tn * 16, 64);
            wmma::mma_sync(fc, fa, fb, fc);
        }
        wmma::store_matrix_sync(cvout + to * 16 * SD + tn * 16, fc, SD, wmma::mem_row_major);
    }
    __syncthreads();

    // fused bias + relu + squash partials + fp16 store (values in regs)
    {
        int i = tid & 63, g = tid >> 6;
        float vv[4];
        float n2 = 0.f;
        #pragma unroll
        for (int k = 0; k < 4; k++) {
            int c = 4 * g + k;
            float hv = fmaxf(cvout[c * SD + i] + gbb[c], 0.f);
            vv[k] = hv;
            n2 += hv * hv;
        }
        PSc[g * SDS + i] = n2;
        __syncthreads();
        if (tid < 64) {
            float t = 0.f;
            #pragma unroll
            for (int g2 = 0; g2 < 16; g2++) t += PSc[g2 * SDS + tid];
            fac[tid] = (t / (1.f + t)) * rsqrtf(t + 1e-8f);
        }
        __syncthreads();
        float f = fac[i];
        #pragma unroll
        for (int k = 0; k < 4; k++)
            xs_h[(4 * g + k) * LDH + i] = __float2half_rn(vv[k] * f);
    }
    __syncthreads();

    for (int L = 0; L < 3; L++)
        cap_layer(64, false, nullptr, g_W1h, b1, g_G1h, g_BW1, g_Bn1,
                  b_basic + (size_t)(L * 128 + b) * 4096, nullptr, sm, tid);
    cap_layer(10, true, W2, nullptr, b2, g_G2h, g_BW2, g_Bn2,
              b_cls + (size_t)b * 640, out + (size_t)b * 640, sm, tid);
}

// ---------------------------------------------------------------------------
static const float* pick(void* const* d_in, const int* in_sizes, int n_in, int sz) {
    for (int i = 0; i < n_in; i++)
        if (in_sizes[i] == sz) return (const float*)d_in[i];
    return nullptr;
}

extern "C" void kernel_launch(void* const* d_in, const int* in_sizes, int n_in,
                              void* d_out, int out_size)
{
    const float* x       = pick(d_in, in_sizes, n_in, 128 * 64 * 64);
    const float* Wb      = pick(d_in, in_sizes, n_in, 64 * 64 * 9);
    const float* bb      = pick(d_in, in_sizes, n_in, 64);
    const float* W1      = pick(d_in, in_sizes, n_in, 4096 * 64);
    const float* b1      = pick(d_in, in_sizes, n_in, 4096);
    const float* W2      = pick(d_in, in_sizes, n_in, 640 * 64);
    const float* b2      = pick(d_in, in_sizes, n_in, 640);
    const float* b_basic = pick(d_in, in_sizes, n_in, 3 * 128 * 64 * 64);
    const float* b_cls   = pick(d_in, in_sizes, n_in, 128 * 10 * 64);
    float* out = (float*)d_out;

    cudaFuncSetAttribute(caps_kernel, cudaFuncAttributeMaxDynamicSharedMemorySize, SMEM_BYTES);
    gram_kernel<<<74, 256>>>(W1, b1, W2, b2, Wb);
    caps_kernel<<<128, 1024, SMEM_BYTES>>>(x, bb, W2, b1, b2, b_basic, b_cls, out);
}

// round 17
// speedup vs baseline: 1.0587x; 1.0387x over previous
#include <cuda_runtime.h>
#include <cuda_fp16.h>
#include <mma.h>
#include <math.h>

using namespace nvcuda;

// ---------------------------------------------------------------------------
// CapsNet forward, fully fused, 1 CTA / batch element, 1024 threads.
// Gram trick: routing never materializes pred.
//   xc[o,c]=sum_i c[o,i]x[c,i];  y[o]=G[o]xc[o]+C*BW[o]  (G=W W^T, fp16)
//   |s|^2=xc.y+C*sB; v=alpha*s;  db[o,i]=alpha*(sum_c y[o,c]x[c,i]+sB)
// R17 = R16 + register-carried E: exp(b) lives in per-thread registers
// across iterations (epilogue thread (gg,ii) produces exactly what the next
// norm pass's (gg,ii) consumes) — the ct smem round-trip for E is deleted;
// only PS partial sums cross threads. Adaptive o-per-warp (nox=1 for O=10).
// Conv via tensor-core im2col with fused epilogue; it==2 skips the G stream;
// xc and db GEMMs on tensor cores.
// ---------------------------------------------------------------------------

#define SD  68                   // fp32 row stride
#define SDS 66                   // PS stride
#define LDH 72                   // half row stride (144B rows)

#define XS_OFF   0               // xs[c][i] fp32 (conv input only)      4352
#define XC_OFF   4352            // xc[o][c] fp32 / db-D / conv-out      4352
#define CT_OFF   8704            // z scratch (it==2)                    4352
#define XSH_OFF  13056           // xs_h[c][i] half 64x72                2304
#define CSH_OFF  15360           // cs_h[o][i] half                      2304
#define YSH_OFF  17664           // ys_h[o][c] half                      2304
#define PS_OFF   19968           // 16x66 fp32                           1056
#define AUX_OFF  21024           // al[64]|sB[64]|CvP[128]
#define IM2_OFF  13056           // im2col half 576x64 overlay
#define SMEM_FLOATS 31552
#define SMEM_BYTES (SMEM_FLOATS * 4)

__device__ __align__(16) __half g_G1h[64 * 64 * 64];
__device__ __align__(16) __half g_G2h[10 * 64 * 64];
__device__ __align__(16) __half g_W1h[64 * 64 * 64];
__device__ __align__(16) __half g_Wbh[64 * 576];
__device__ float g_BW1[64 * 64];
__device__ float g_Bn1[64];
__device__ float g_BW2[10 * 64];
__device__ float g_Bn2[16];

// ---------------------------------------------------------------------------
__global__ void gram_kernel(const float* __restrict__ W1, const float* __restrict__ b1,
                            const float* __restrict__ W2, const float* __restrict__ b2,
                            const float* __restrict__ Wb)
{
    __shared__ float ws[64 * SD];
    __shared__ float bsv[64];
    int blk = blockIdx.x;
    const float* W;
    const float* bias;
    __half* G; float* BW; float* Bn;
    int o;
    if (blk < 64) { o = blk;      W = W1; bias = b1; G = g_G1h + o * 4096; BW = g_BW1 + o * 64; Bn = g_Bn1 + o; }
    else          { o = blk - 64; W = W2; bias = b2; G = g_G2h + o * 4096; BW = g_BW2 + o * 64; Bn = g_Bn2 + o; }
    int tid = threadIdx.x;  // 256

    for (int p = tid; p < 64 * 16; p += 256) {
        int d = p >> 4, q = p & 15;
        float4 v = ((const float4*)(W + (o * 64 + d) * 64))[q];
        ws[d * SD + q * 4 + 0] = v.x;
        ws[d * SD + q * 4 + 1] = v.y;
        ws[d * SD + q * 4 + 2] = v.z;
        ws[d * SD + q * 4 + 3] = v.w;
    }
    if (tid < 64) bsv[tid] = bias[o * 64 + tid];
    __syncthreads();

    for (int p = tid; p < 64 * 16; p += 256) {
        int c = p >> 4, c4 = (p & 15) * 4;
        float a0 = 0.f, a1 = 0.f, a2 = 0.f, a3 = 0.f;
        #pragma unroll 4
        for (int d = 0; d < 64; d++) {
            float wc = ws[d * SD + c];
            a0 += wc * ws[d * SD + c4 + 0];
            a1 += wc * ws[d * SD + c4 + 1];
            a2 += wc * ws[d * SD + c4 + 2];
            a3 += wc * ws[d * SD + c4 + 3];
        }
        G[c * 64 + c4 + 0] = __float2half_rn(a0);
        G[c * 64 + c4 + 1] = __float2half_rn(a1);
        G[c * 64 + c4 + 2] = __float2half_rn(a2);
        G[c * 64 + c4 + 3] = __float2half_rn(a3);
    }
    if (blk < 64) {
        for (int p = tid; p < 2048; p += 256) {
            int d = p >> 5, c2 = (p & 31) * 2;
            __half2 hv = __floats2half2_rn(ws[d * SD + c2], ws[d * SD + c2 + 1]);
            *((__half2*)(g_W1h + ((size_t)o << 12) + d * 64 + c2)) = hv;
        }
        for (int p = tid; p < 576; p += 256)
            g_Wbh[o * 576 + p] = __float2half_rn(Wb[o * 576 + p]);
    }
    if (tid < 64) {
        float acc = 0.f;
        for (int d = 0; d < 64; d++) acc += bsv[d] * ws[d * SD + tid];
        BW[tid] = acc;
    }
    if (tid == 64) {
        float acc = 0.f;
        for (int d = 0; d < 64; d++) acc += bsv[d] * bsv[d];
        *Bn = acc;
    }
}

// ---------------------------------------------------------------------------
// One capsule layer, 3 routing iterations. O = 64 or 10 (even).
// ---------------------------------------------------------------------------
__device__ __forceinline__ void cap_layer(
    int O, bool is_final,
    const float* __restrict__ W2f, const __half* __restrict__ W1h,
    const float* __restrict__ bias,
    const __half* __restrict__ Gh, const float* __restrict__ BW, const float* __restrict__ Bn,
    const float* __restrict__ b0, float* __restrict__ outp,
    float* sm, int tid)
{
    float* xc  = sm + XC_OFF;          // xc, then db-D
    float* zbS = sm + CT_OFF;          // z scratch at it==2
    float* PS  = sm + PS_OFF;
    float* al  = sm + AUX_OFF;
    float* sB  = sm + AUX_OFF + 64;
    float* CvP = sm + AUX_OFF + 128;
    __half* xs_h = (__half*)(sm + XSH_OFF);
    __half* cs_h = (__half*)(sm + CSH_OFF);
    __half* ys_h = (__half*)(sm + YSH_OFF);

    const int w = tid >> 5, lane = tid & 31;
    const int ii = tid & 63, gg = tid >> 6;
    const int ngrp4 = (O + 3) >> 2;
    const int nox = (O > 32) ? 2 : 1;            // capsules per warp in stream phases
    const int o0 = w * nox;
    const int seg = lane & 7, rgrp = lane >> 3;

    // ---- E0 = exp(b0) (unnormalized) -> REGISTERS; PS partial sums ----
    float eR0 = 0.f, eR1 = 0.f, eR2 = 0.f, eR3 = 0.f;
    if (gg < ngrp4) {
        int ob = gg << 2;
        eR0 = __expf(b0[ob * 64 + ii]);
        eR1 = (ob + 1 < O) ? __expf(b0[(ob + 1) * 64 + ii]) : 0.f;
        eR2 = (ob + 2 < O) ? __expf(b0[(ob + 2) * 64 + ii]) : 0.f;
        eR3 = (ob + 3 < O) ? __expf(b0[(ob + 3) * 64 + ii]) : 0.f;
        PS[gg * SDS + ii] = eR0 + eR1 + eR2 + eR3;
    }
    __syncthreads();

    for (int it = 0; it < 3; it++) {
        // ---- norm pass: cs_h[o][i] = E*ginv (fp16) from registers ----
        {
            float s = 0.f;
            for (int g2 = 0; g2 < ngrp4; g2++) s += PS[g2 * SDS + ii];
            float gi = 1.f / s;
            float c0 = 0.f, c1 = 0.f, c2 = 0.f, c3 = 0.f;
            if (gg < ngrp4) {
                c0 = eR0 * gi; c1 = eR1 * gi; c2 = eR2 * gi; c3 = eR3 * gi;
                cs_h[((gg << 2) + 0) * LDH + ii] = __float2half_rn(c0);
                cs_h[((gg << 2) + 1) * LDH + ii] = __float2half_rn(c1);
                cs_h[((gg << 2) + 2) * LDH + ii] = __float2half_rn(c2);
                cs_h[((gg << 2) + 3) * LDH + ii] = __float2half_rn(c3);
            }
            #pragma unroll
            for (int k = 16; k; k >>= 1) {
                c0 += __shfl_xor_sync(0xffffffffu, c0, k);
                c1 += __shfl_xor_sync(0xffffffffu, c1, k);
                c2 += __shfl_xor_sync(0xffffffffu, c2, k);
                c3 += __shfl_xor_sync(0xffffffffu, c3, k);
            }
            if (lane == 0 && gg < ngrp4) {
                float* dst = CvP + ((w & 1) << 6) + (gg << 2);
                dst[0] = c0; dst[1] = c1; dst[2] = c2; dst[3] = c3;
            }
        }
        __syncthreads();

        // ---- xc = c @ x^T via tensor cores (16 warps, 1 tile each) ----
        if (w < 16 && ((w >> 2) << 4) < O) {
            int to = w >> 2, tc = w & 3;
            wmma::fragment<wmma::accumulator, 16, 16, 16, float> fc;
            wmma::fill_fragment(fc, 0.f);
            #pragma unroll
            for (int k = 0; k < 4; k++) {
                wmma::fragment<wmma::matrix_a, 16, 16, 16, __half, wmma::row_major> fa;
                wmma::fragment<wmma::matrix_b, 16, 16, 16, __half, wmma::col_major> fb;
                wmma::load_matrix_sync(fa, cs_h + to * 16 * LDH + k * 16, LDH);
                wmma::load_matrix_sync(fb, xs_h + tc * 16 * LDH + k * 16, LDH);
                wmma::mma_sync(fc, fa, fb, fc);
            }
            wmma::store_matrix_sync(xc + to * 16 * SD + tc * 16, fc, SD, wmma::mem_row_major);
        }
        __syncthreads();

        if (it < 2) {
            // ---- y phase: per-o G GEMV with inline reductions ----
            if (o0 < O) {
                for (int oo = 0; oo < nox; oo++) {
                    int o = o0 + oo;
                    float cf = CvP[o] + CvP[64 + o];
                    const __half* Gp = Gh + ((size_t)o << 12) + (seg << 3);
                    float4 xq0 = *(const float4*)(xc + o * SD + seg * 8);
                    float4 xq1 = *(const float4*)(xc + o * SD + seg * 8 + 4);
                    float nq = 0.f, sbq = 0.f;
                    #pragma unroll 8
                    for (int rb = 0; rb < 64; rb += 4) {
                        int r = rb + rgrp;
                        uint4 g = *(const uint4*)(Gp + (r << 6));
                        float2 t0 = __half22float2(*(__half2*)&g.x);
                        float2 t1 = __half22float2(*(__half2*)&g.y);
                        float2 t2 = __half22float2(*(__half2*)&g.z);
                        float2 t3 = __half22float2(*(__half2*)&g.w);
                        float p = t0.x * xq0.x + t0.y * xq0.y + t1.x * xq0.z + t1.y * xq0.w
                                + t2.x * xq1.x + t2.y * xq1.y + t3.x * xq1.z + t3.y * xq1.w;
                        p += __shfl_xor_sync(0xffffffffu, p, 1);
                        p += __shfl_xor_sync(0xffffffffu, p, 2);
                        p += __shfl_xor_sync(0xffffffffu, p, 4);   // (G xc)[r]
                        float bwv = BW[o * 64 + r];
                        float yv = p + cf * bwv;
                        float xcr = xc[o * SD + r];
                        nq += yv * xcr;
                        sbq += bwv * xcr;
                        if (seg == 0)
                            ys_h[o * LDH + r] = __float2half_rn(yv);
                    }
                    nq  += __shfl_xor_sync(0xffffffffu, nq, 8);
                    nq  += __shfl_xor_sync(0xffffffffu, nq, 16);
                    sbq += __shfl_xor_sync(0xffffffffu, sbq, 8);
                    sbq += __shfl_xor_sync(0xffffffffu, sbq, 16);
                    if (lane == 0) {
                        float sbf = sbq + cf * Bn[o];
                        float nn = nq + cf * sbf;
                        sB[o] = sbf;
                        al[o] = (nn / (1.f + nn)) * rsqrtf(nn + 1e-8f);
                    }
                }
            }
            __syncthreads();

            // ---- db = y @ x via tensor cores -> D in xc region ----
            if (w < 16 && ((w >> 2) << 4) < O) {
                int to = w >> 2, ti = w & 3;
                wmma::fragment<wmma::accumulator, 16, 16, 16, float> fc;
                wmma::fill_fragment(fc, 0.f);
                #pragma unroll
                for (int k = 0; k < 4; k++) {
                    wmma::fragment<wmma::matrix_a, 16, 16, 16, __half, wmma::row_major> fa;
                    wmma::fragment<wmma::matrix_b, 16, 16, 16, __half, wmma::row_major> fb;
                    wmma::load_matrix_sync(fa, ys_h + to * 16 * LDH + k * 16, LDH);
                    wmma::load_matrix_sync(fb, xs_h + k * 16 * LDH + ti * 16, LDH);
                    wmma::mma_sync(fc, fa, fb, fc);
                }
                wmma::store_matrix_sync(xc + to * 16 * SD + ti * 16, fc, SD, wmma::mem_row_major);
            }
            __syncthreads();

            // ---- epilogue: new E (registers) = c * exp(al*(db+sB)); PS ----
            if (gg < ngrp4) {
                int ob = gg << 2;
                float dv, cc;
                dv = xc[(ob + 0) * SD + ii];
                cc = __half2float(cs_h[(ob + 0) * LDH + ii]);
                eR0 = cc * __expf(al[ob + 0] * (dv + sB[ob + 0]));
                if (ob + 1 < O) {
                    dv = xc[(ob + 1) * SD + ii];
                    cc = __half2float(cs_h[(ob + 1) * LDH + ii]);
                    eR1 = cc * __expf(al[ob + 1] * (dv + sB[ob + 1]));
                } else eR1 = 0.f;
                if (ob + 2 < O) {
                    dv = xc[(ob + 2) * SD + ii];
                    cc = __half2float(cs_h[(ob + 2) * LDH + ii]);
                    eR2 = cc * __expf(al[ob + 2] * (dv + sB[ob + 2]));
                } else eR2 = 0.f;
                if (ob + 3 < O) {
                    dv = xc[(ob + 3) * SD + ii];
                    cc = __half2float(cs_h[(ob + 3) * LDH + ii]);
                    eR3 = cc * __expf(al[ob + 3] * (dv + sB[ob + 3]));
                } else eR3 = 0.f;
                PS[gg * SDS + ii] = eR0 + eR1 + eR2 + eR3;
            }
            __syncthreads();
        } else if (!is_final) {
            // ---- it==2: z = W1 xc + Cv*B; |s|^2 = sum z^2 (no G stream) ----
            float* zb = zbS;
            if (o0 < O) {
                for (int oo = 0; oo < nox; oo++) {
                    int o = o0 + oo;
                    float cf = CvP[o] + CvP[64 + o];
                    float4 xq0 = *(const float4*)(xc + o * SD + seg * 8);
                    float4 xq1 = *(const float4*)(xc + o * SD + seg * 8 + 4);
                    const __half* Wp = W1h + ((size_t)o << 12) + (seg << 3);
                    float zz = 0.f;
                    #pragma unroll 8
                    for (int db_ = 0; db_ < 64; db_ += 4) {
                        int d = db_ + rgrp;
                        uint4 g = *(const uint4*)(Wp + (d << 6));
                        float2 t0 = __half22float2(*(__half2*)&g.x);
                        float2 t1 = __half22float2(*(__half2*)&g.y);
                        float2 t2 = __half22float2(*(__half2*)&g.z);
                        float2 t3 = __half22float2(*(__half2*)&g.w);
                        float p = t0.x * xq0.x + t0.y * xq0.y + t1.x * xq0.z + t1.y * xq0.w
                                + t2.x * xq1.x + t2.y * xq1.y + t3.x * xq1.z + t3.y * xq1.w;
                        p += __shfl_xor_sync(0xffffffffu, p, 1);
                        p += __shfl_xor_sync(0xffffffffu, p, 2);
                        p += __shfl_xor_sync(0xffffffffu, p, 4);
                        if (seg == 0) {
                            float z = p + cf * bias[o * 64 + d];
                            zb[o * SD + d] = z;
                            zz += z * z;
                        }
                    }
                    #pragma unroll
                    for (int k = 16; k; k >>= 1)
                        zz += __shfl_xor_sync(0xffffffffu, zz, k);
                    float av = (zz / (1.f + zz)) * rsqrtf(zz + 1e-8f);
                    __syncwarp();
                    float z0 = zb[o * SD + lane], z1 = zb[o * SD + lane + 32];
                    xs_h[lane * LDH + o]        = __float2half_rn(av * z0);
                    xs_h[(lane + 32) * LDH + o] = __float2half_rn(av * z1);
                }
            }
            __syncthreads();
        } else {
            // ---- final it==2: z via fp32 W2; v = al*z -> gmem ----
            float* zb = zbS;
            if (o0 < O) {
                const int s16 = lane & 15, rg2 = lane >> 4;
                for (int oo = 0; oo < nox; oo++) {
                    int o = o0 + oo;
                    float cf = CvP[o] + CvP[64 + o];
                    float4 xq = *(const float4*)(xc + o * SD + s16 * 4);
                    const float* Wp = W2f + (size_t)(o * 64) * 64 + s16 * 4;
                    float zz = 0.f;
                    #pragma unroll 8
                    for (int db_ = 0; db_ < 64; db_ += 2) {
                        int d = db_ + rg2;
                        float4 wv = *(const float4*)(Wp + (d << 6));
                        float p = wv.x * xq.x + wv.y * xq.y + wv.z * xq.z + wv.w * xq.w;
                        p += __shfl_xor_sync(0xffffffffu, p, 1);
                        p += __shfl_xor_sync(0xffffffffu, p, 2);
                        p += __shfl_xor_sync(0xffffffffu, p, 4);
                        p += __shfl_xor_sync(0xffffffffu, p, 8);
                        if (s16 == 0) {
                            float z = p + cf * bias[o * 64 + d];
                            zb[o * SD + d] = z;
                            zz += z * z;
                        }
                    }
                    #pragma unroll
                    for (int k = 16; k; k >>= 1)
                        zz += __shfl_xor_sync(0xffffffffu, zz, k);
                    float av = (zz / (1.f + zz)) * rsqrtf(zz + 1e-8f);
                    __syncwarp();
                    outp[o * 64 + lane]      = av * zb[o * SD + lane];
                    outp[o * 64 + lane + 32] = av * zb[o * SD + lane + 32];
                }
            }
            __syncthreads();
        }
    }
}

// ---------------------------------------------------------------------------
// Main fused kernel: tensor-core conv3x3 (im2col) + fused relu/squash,
// then 3+1 capsule layers.
// ---------------------------------------------------------------------------
__global__ void __launch_bounds__(1024, 1)
caps_kernel(const float* __restrict__ gx,  const float* __restrict__ gbb,
            const float* __restrict__ W2,  const float* __restrict__ b1,
            const float* __restrict__ b2,
            const float* __restrict__ b_basic, const float* __restrict__ b_cls,
            float* __restrict__ out)
{
    extern __shared__ float sm[];
    int tid = threadIdx.x;
    int b = blockIdx.x;
    float* xs    = sm + XS_OFF;
    float* cvout = sm + XC_OFF;
    float* PSc   = sm + PS_OFF;
    float* fac   = sm + AUX_OFF;
    __half* im2  = (__half*)(sm + IM2_OFF);
    __half* xs_h = (__half*)(sm + XSH_OFF);
    const int w = tid >> 5;

    // load x[b]: xs[c][i]
    const float* xb = gx + (size_t)b * 4096;
    {
        int c = tid >> 4, q = tid & 15;
        float4 v = ((const float4*)(xb + c * 64))[q];
        xs[c * SD + q * 4 + 0] = v.x;
        xs[c * SD + q * 4 + 1] = v.y;
        xs[c * SD + q * 4 + 2] = v.z;
        xs[c * SD + q * 4 + 3] = v.w;
    }
    __syncthreads();

    // im2col (div-free): thread handles column n for 4 ci values; 3x3 unrolled.
    {
        int n = tid & 63, cig = tid >> 6;
        int y = n >> 3, x = n & 7;
        for (int cb = 0; cb < 64; cb += 16) {
            int ci = cb + cig;
            const float* xrow = xs + ci * SD;
            __half* dst = im2 + (ci * 9) * 64 + n;
            #pragma unroll
            for (int ky = 0; ky < 3; ky++) {
                int yy = y + ky - 1;
                bool yok = (unsigned)yy < 8u;
                #pragma unroll
                for (int kx = 0; kx < 3; kx++) {
                    int xx = x + kx - 1;
                    float v = (yok && (unsigned)xx < 8u) ? xrow[yy * 8 + xx] : 0.f;
                    dst[(ky * 3 + kx) * 64] = __float2half_rn(v);
                }
            }
        }
    }
    __syncthreads();

    // conv GEMM: C[co][n] = sum_k Wbh[co][k] * im2[k][n]
    if (w < 16) {
        int to = w >> 2, tn = w & 3;
        wmma::fragment<wmma::accumulator, 16, 16, 16, float> fc;
        wmma::fill_fragment(fc, 0.f);
        for (int k = 0; k < 36; k++) {
            wmma::fragment<wmma::matrix_a, 16, 16, 16, __half, wmma::row_major> fa;
            wmma::fragment<wmma::matrix_b, 16, 16, 16, __half, wmma::row_major> fb;
            wmma::load_matrix_sync(fa, g_Wbh + to * 16 * 576 + k * 16, 576);
            wmma::load_matrix_sync(fb, im2 + k * 16 * 64 + tn * 16, 64);
            wmma::mma_sync(fc, fa, fb, fc);
        }
        wmma::store_matrix_sync(cvout + to * 16 * SD + tn * 16, fc, SD, wmma::mem_row_major);
    }
    __syncthreads();

    // fused bias + relu + squash partials + fp16 store (values in regs)
    {
        int i = tid & 63, g = tid >> 6;
        float vv[4];
        float n2 = 0.f;
        #pragma unroll
        for (int k = 0; k < 4; k++) {
            int c = 4 * g + k;
            float hv = fmaxf(cvout[c * SD + i] + gbb[c], 0.f);
            vv[k] = hv;
            n2 += hv * hv;
        }
        PSc[g * SDS + i] = n2;
        __syncthreads();
        if (tid < 64) {
            float t = 0.f;
            #pragma unroll
            for (int g2 = 0; g2 < 16; g2++) t += PSc[g2 * SDS + tid];
            fac[tid] = (t / (1.f + t)) * rsqrtf(t + 1e-8f);
        }
        __syncthreads();
        float f = fac[i];
        #pragma unroll
        for (int k = 0; k < 4; k++)
            xs_h[(4 * g + k) * LDH + i] = __float2half_rn(vv[k] * f);
    }
    __syncthreads();

    for (int L = 0; L < 3; L++)
        cap_layer(64, false, nullptr, g_W1h, b1, g_G1h, g_BW1, g_Bn1,
                  b_basic + (size_t)(L * 128 + b) * 4096, nullptr, sm, tid);
    cap_layer(10, true, W2, nullptr, b2, g_G2h, g_BW2, g_Bn2,
              b_cls + (size_t)b * 640, out + (size_t)b * 640, sm, tid);
}

// ---------------------------------------------------------------------------
static const float* pick(void* const* d_in, const int* in_sizes, int n_in, int sz) {
    for (int i = 0; i < n_in; i++)
        if (in_sizes[i] == sz) return (const float*)d_in[i];
    return nullptr;
}

extern "C" void kernel_launch(void* const* d_in, const int* in_sizes, int n_in,
                              void* d_out, int out_size)
{
    const float* x       = pick(d_in, in_sizes, n_in, 128 * 64 * 64);
    const float* Wb      = pick(d_in, in_sizes, n_in, 64 * 64 * 9);
    const float* bb      = pick(d_in, in_sizes, n_in, 64);
    const float* W1      = pick(d_in, in_sizes, n_in, 4096 * 64);
    const float* b1      = pick(d_in, in_sizes, n_in, 4096);
    const float* W2      = pick(d_in, in_sizes, n_in, 640 * 64);
    const float* b2      = pick(d_in, in_sizes, n_in, 640);
    const float* b_basic = pick(d_in, in_sizes, n_in, 3 * 128 * 64 * 64);
    const float* b_cls   = pick(d_in, in_sizes, n_in, 128 * 10 * 64);
    float* out = (float*)d_out;

    cudaFuncSetAttribute(caps_kernel, cudaFuncAttributeMaxDynamicSharedMemorySize, SMEM_BYTES);
    gram_kernel<<<74, 256>>>(W1, b1, W2, b2, Wb);
    caps_kernel<<<128, 1024, SMEM_BYTES>>>(x, bb, W2, b1, b2, b_basic, b_cls, out);
}